// round 17
// baseline (speedup 1.0000x reference)
#include <cuda_runtime.h>

#define NN 100000
#define EE 1600000
#define DD 64
#define GG 64
#define OUTC 10
#define NB ((NN + 255) / 256)   // 391 scan blocks

// ---- scratch ----
__device__ int     g_is64;
__device__ int     g_batch[NN];
__device__ int     g_deg[NN];      // zeroed by trailing fold (and module load)
__device__ int     g_cursor[NN];   // zeroed by trailing fold (and module load)
__device__ int     g_rowstart[NN + 1];
__device__ unsigned long long g_scan_state[NB];  // lookback: flag(2b)<<62 | value
__device__ int     g_adj[EE];
__device__ float   g_inv_deg[NN];
__device__ float4  g_agg[(size_t)NN * (DD / 4)];
__device__ float4  g_h0 [(size_t)NN * (DD / 4)];
__device__ float4  g_h1 [(size_t)NN * (DD / 4)];
__device__ float   g_pool[GG * DD];

__device__ __forceinline__ int load_idx(const void* p, size_t i, int is64) {
    return is64 ? (int)((const long long*)p)[i] : ((const int*)p)[i];
}

// packed fp32 add: d.lo += v.lo, d.hi += v.hi (1 instr for 2 dims)
__device__ __forceinline__ void addf32x2(unsigned long long& d, unsigned long long v) {
    asm("add.rn.f32x2 %0, %0, %1;" : "+l"(d) : "l"(v));
}

// ---- launch 1: dtype detect + batch cvt + degree histogram + scan-state reset
__global__ void prep_deg_kernel(const void* __restrict__ ei,
                                const void* __restrict__ bat) {
    __shared__ int s_is64;
    if (threadIdx.x == 0) {
        const unsigned int* w = (const unsigned int*)ei;
        int is64 = 1;
        for (int i = 0; i < 16; i++)
            if (w[2 * i + 1] != 0u) { is64 = 0; break; }
        s_is64 = is64;
        if (blockIdx.x == 0) g_is64 = is64;
    }
    __syncthreads();
    int is64 = s_is64;
    int e = blockIdx.x * blockDim.x + threadIdx.x;
    if (e < NB) g_scan_state[e] = 0ull;
    if (e < NN) g_batch[e] = load_idx(bat, e, is64);
    if (e < EE) atomicAdd(&g_deg[load_idx(ei, (size_t)EE + e, is64)], 1);
}

// ---- launch 2: single-pass exclusive scan (decoupled lookback) --------------
#define FLAG_AGG  (1ull << 62)
#define FLAG_PREF (2ull << 62)
__global__ void scan_kernel() {
    __shared__ int s[256];
    __shared__ int s_excl;
    int tid = threadIdx.x;
    int bid = blockIdx.x;
    int i = bid * 256 + tid;
    int v = (i < NN) ? g_deg[i] : 0;
    s[tid] = v;
    __syncthreads();
    #pragma unroll
    for (int off = 1; off < 256; off <<= 1) {
        int t = (tid >= off) ? s[tid - off] : 0;
        __syncthreads();
        s[tid] += t;
        __syncthreads();
    }
    if (tid == 0) {
        int total = s[255];
        if (bid == 0) {
            atomicExch(&g_scan_state[0], FLAG_PREF | (unsigned)total);
            s_excl = 0;
        } else {
            atomicExch(&g_scan_state[bid], FLAG_AGG | (unsigned)total);
            int excl = 0;
            int j = bid - 1;
            while (true) {
                unsigned long long st =
                    *(volatile unsigned long long*)&g_scan_state[j];
                if (!(st >> 62)) { __nanosleep(20); continue; }
                excl += (int)(st & 0xFFFFFFFFu);
                if (st & FLAG_PREF) break;
                j--;
            }
            atomicExch(&g_scan_state[bid], FLAG_PREF | (unsigned)(excl + total));
            s_excl = excl;
        }
    }
    __syncthreads();
    int ex = s_excl;
    if (i < NN) {
        g_rowstart[i] = ex + s[tid] - v;
        g_inv_deg[i] = 1.0f / (float)max(v, 1);
    }
    if (i == 0) g_rowstart[NN] = EE;
}

// ---- launch 3: adjacency fill (verified near L2-RMW bound: 25us) ------------
__global__ void csr_fill_kernel(const void* __restrict__ ei) {
    int e = blockIdx.x * blockDim.x + threadIdx.x;
    if (e < EE) {
        int is64 = g_is64;
        int src = load_idx(ei, e, is64);
        int dst = load_idx(ei, (size_t)EE + e, is64);
        int pos = atomicAdd(&g_cursor[dst], 1);
        g_adj[g_rowstart[dst] + pos] = src;
    }
}

// ---- launch 4 (PROFILED): gather-mean, fp32 + packed f32x2 accumulation -----
// One warp per node, lane owns one float2 (8B). Per edge per lane:
// idx LDG + IMAD + LDG.64 + 1 ADD.F32X2 (was + 2 cvt + 2 FADD in R16 —
// issue-bound at 62%, so instruction count is the lever).
__global__ void gather_kernel(int sel, const float* __restrict__ x) {
    int gtid = blockIdx.x * blockDim.x + threadIdx.x;
    int node = gtid >> 5;
    if (node >= NN) return;
    int lane = threadIdx.x & 31;

    const unsigned long long* h64 =
        (sel == 0) ? (const unsigned long long*)x
      : (sel == 1) ? (const unsigned long long*)g_h0
                   : (const unsigned long long*)g_h1;

    int rs = g_rowstart[node];
    int re = g_rowstart[node + 1];
    unsigned long long a0 = 0ull, a1 = 0ull;   // two chains break latency
    int e = rs;
    for (; e + 8 <= re; e += 8) {
        int s0 = g_adj[e+0], s1 = g_adj[e+1], s2 = g_adj[e+2], s3 = g_adj[e+3];
        int s4 = g_adj[e+4], s5 = g_adj[e+5], s6 = g_adj[e+6], s7 = g_adj[e+7];
        unsigned long long v0 = h64[(size_t)s0 * 32 + lane];
        unsigned long long v1 = h64[(size_t)s1 * 32 + lane];
        unsigned long long v2 = h64[(size_t)s2 * 32 + lane];
        unsigned long long v3 = h64[(size_t)s3 * 32 + lane];
        unsigned long long v4 = h64[(size_t)s4 * 32 + lane];
        unsigned long long v5 = h64[(size_t)s5 * 32 + lane];
        unsigned long long v6 = h64[(size_t)s6 * 32 + lane];
        unsigned long long v7 = h64[(size_t)s7 * 32 + lane];
        addf32x2(a0, v0); addf32x2(a1, v1);
        addf32x2(a0, v2); addf32x2(a1, v3);
        addf32x2(a0, v4); addf32x2(a1, v5);
        addf32x2(a0, v6); addf32x2(a1, v7);
    }
    for (; e < re; e++) {
        addf32x2(a0, h64[(size_t)g_adj[e] * 32 + lane]);
    }
    addf32x2(a0, a1);
    float2 f = *(float2*)&a0;
    float inv = g_inv_deg[node];
    ((float2*)g_agg)[(size_t)node * 32 + lane] = make_float2(f.x * inv, f.y * inv);
}

// ---- register-tiled linear: out = relu([agg|h]@[Wl;Wr] + bl) ----------------
// 256 threads = 16x16, 4x4 register tile, two k=64 passes.
// sel==2 re-zeros deg/cursor for the next call/replay.
__global__ void linear_kernel(int sel, const float* __restrict__ x,
                              const float* __restrict__ Wl,
                              const float* __restrict__ bl,
                              const float* __restrict__ Wr) {
    __shared__ __align__(16) float sA[DD][68];
    __shared__ __align__(16) float sW[DD][DD];
    __shared__ float sb[DD];

    const float* hin  = (sel == 0) ? x
                       : (sel == 1) ? (const float*)g_h0 : (const float*)g_h1;
    float*       hout = (sel == 0) ? (float*)g_h0
                       : (sel == 1) ? (float*)g_h1 : (float*)g_h0;

    int tid  = threadIdx.x;
    int base = blockIdx.x * 64;
    int tc = tid & 15;
    int tr = tid >> 4;
    if (tid < DD) sb[tid] = bl[tid];

    if (sel == 2 && tid < 64) {          // trailing state-reset fold
        int n = base + tid;
        if (n < NN) { g_deg[n] = 0; g_cursor[n] = 0; }
    }

    float acc[4][4];
    #pragma unroll
    for (int i = 0; i < 4; i++)
        #pragma unroll
        for (int j = 0; j < 4; j++) acc[i][j] = 0.f;

    int r_st   = tid >> 2;
    int row_st = base + r_st;
    int k4b    = (tid & 3) * 4;

    #pragma unroll
    for (int pass = 0; pass < 2; pass++) {
        const float* A = (pass == 0) ? (const float*)g_agg : hin;
        const float* W = (pass == 0) ? Wl : Wr;
        for (int i = tid; i < DD * DD; i += 256) sW[i >> 6][i & 63] = W[i];
        #pragma unroll
        for (int j = 0; j < 4; j++) {
            int k4 = k4b + j;
            float4 v = make_float4(0.f, 0.f, 0.f, 0.f);
            if (row_st < NN) v = ((const float4*)A)[(size_t)row_st * (DD/4) + k4];
            sA[k4 * 4 + 0][r_st] = v.x;
            sA[k4 * 4 + 1][r_st] = v.y;
            sA[k4 * 4 + 2][r_st] = v.z;
            sA[k4 * 4 + 3][r_st] = v.w;
        }
        __syncthreads();
        #pragma unroll 8
        for (int k = 0; k < DD; k++) {
            float4 a4 = *(const float4*)&sA[k][tr * 4];
            float4 w4 = *(const float4*)&sW[k][tc * 4];
            float av[4] = { a4.x, a4.y, a4.z, a4.w };
            float wv[4] = { w4.x, w4.y, w4.z, w4.w };
            #pragma unroll
            for (int i = 0; i < 4; i++)
                #pragma unroll
                for (int j = 0; j < 4; j++)
                    acc[i][j] = fmaf(av[i], wv[j], acc[i][j]);
        }
        __syncthreads();
    }

    #pragma unroll
    for (int i = 0; i < 4; i++) {
        int row = base + tr * 4 + i;
        if (row < NN) {
            float4 o;
            o.x = fmaxf(acc[i][0] + sb[tc * 4 + 0], 0.f);
            o.y = fmaxf(acc[i][1] + sb[tc * 4 + 1], 0.f);
            o.z = fmaxf(acc[i][2] + sb[tc * 4 + 2], 0.f);
            o.w = fmaxf(acc[i][3] + sb[tc * 4 + 3], 0.f);
            *(float4*)&hout[(size_t)row * DD + tc * 4] = o;
        }
    }
}

// ---- global mean pool (batch sorted -> binary search) -----------------------
__global__ void pool_kernel() {
    int g = blockIdx.x;
    int col = threadIdx.x;
    int a = 0, b = NN;
    while (a < b) { int m = (a + b) >> 1; if (g_batch[m] < g) a = m + 1; else b = m; }
    int start = a;
    b = NN;
    while (a < b) { int m = (a + b) >> 1; if (g_batch[m] < g + 1) a = m + 1; else b = m; }
    int end = a;
    float acc = 0.f;
    const float* h = (const float*)g_h0;
    for (int n = start; n < end; n++) acc += h[(size_t)n * DD + col];
    g_pool[g * DD + col] = acc / fmaxf((float)(end - start), 1.f);
}

// ---- final MLP --------------------------------------------------------------
__global__ void mlp_kernel(const float* __restrict__ l0W,
                           const float* __restrict__ l0b,
                           const float* __restrict__ outW,
                           const float* __restrict__ outb,
                           float* __restrict__ out) {
    __shared__ float sg[DD];
    __shared__ float sh[DD];
    int gi = blockIdx.x, t = threadIdx.x;
    sg[t] = g_pool[gi * DD + t];
    __syncthreads();
    float acc = l0b[t];
    #pragma unroll
    for (int k = 0; k < DD; k++) acc = fmaf(sg[k], l0W[k * DD + t], acc);
    sh[t] = fmaxf(acc, 0.f);
    __syncthreads();
    if (t < OUTC) {
        float a = outb[t];
        #pragma unroll
        for (int k = 0; k < DD; k++) a = fmaf(sh[k], outW[k * OUTC + t], a);
        out[gi * OUTC + t] = a;
    }
}

extern "C" void kernel_launch(void* const* d_in, const int* in_sizes, int n_in,
                              void* d_out, int out_size) {
    const float* x    = (const float*)d_in[0];
    const void*  ei   = d_in[1];
    const void*  bat  = d_in[2];
    const float* c_Wl[3] = { (const float*)d_in[3], (const float*)d_in[6], (const float*)d_in[9]  };
    const float* c_bl[3] = { (const float*)d_in[4], (const float*)d_in[7], (const float*)d_in[10] };
    const float* c_Wr[3] = { (const float*)d_in[5], (const float*)d_in[8], (const float*)d_in[11] };
    const float* l0W  = (const float*)d_in[12];
    const float* l0b  = (const float*)d_in[13];
    const float* outW = (const float*)d_in[14];
    const float* outb = (const float*)d_in[15];
    float* out = (float*)d_out;

    // CSR build: 3 launches, gather L0 sits at profile slot 4
    prep_deg_kernel<<<(EE + 255) / 256, 256>>>(ei, bat);
    scan_kernel<<<NB, 256>>>();
    csr_fill_kernel<<<(EE + 255) / 256, 256>>>(ei);

    // 3 SAGE layers: fp32 f32x2 gather-mean then register-tiled linear
    const int gather_blocks = (NN * 32 + 255) / 256;
    const int linear_blocks = (NN + 63) / 64;
    for (int l = 0; l < 3; l++) {
        gather_kernel<<<gather_blocks, 256>>>(l, x);
        linear_kernel<<<linear_blocks, 256>>>(l, x, c_Wl[l], c_bl[l], c_Wr[l]);
    }

    // pooling + MLP
    pool_kernel<<<GG, DD>>>();
    mlp_kernel<<<GG, DD>>>(l0W, l0b, outW, outb, out);
}